// round 13
// baseline (speedup 1.0000x reference)
#include <cuda_runtime.h>

// ---------------------------------------------------------------------------
// HiLo attention, tf32 tensor-core version.
// Shapes: B=4, C=512, H=W=64 (HW=4096, BHW=16384), heads 4+4, head_dim 64.
// ---------------------------------------------------------------------------

#define BATCH   4
#define CDIM    512
#define BHW     16384
#define BG      4096
#define SCALE   0.125f                 // 64^-0.5
#define QSCALE  0.18033688f            // SCALE * log2(e)

// Scratch
__device__ float g_X[BHW * CDIM];
__device__ float g_pooled[BG * CDIM];
__device__ float g_QKV[BHW * 768];
__device__ float g_Ql[BHW * 256];
__device__ float g_KVl[BG * 512];
__device__ float g_HiOut[BHW * 256];
__device__ float g_LoOut[BHW * 256];
__device__ float g_HiFi[BHW * 256];
__device__ float g_LoFi[BHW * 256];

// ---------------------------------------------------------------------------
// helpers
// ---------------------------------------------------------------------------
__device__ __forceinline__ unsigned f2tf(float f) {
    unsigned u;
    asm("cvt.rna.tf32.f32 %0, %1;" : "=r"(u) : "f"(f));
    return u;
}
__device__ __forceinline__ uint4 f2tf4(float4 v) {
    uint4 u;
    u.x = f2tf(v.x); u.y = f2tf(v.y); u.z = f2tf(v.z); u.w = f2tf(v.w);
    return u;
}
__device__ __forceinline__ float ex2(float x) {
    float r;
    asm("ex2.approx.ftz.f32 %0, %1;" : "=f"(r) : "f"(x));
    return r;
}
__device__ __forceinline__ void mma_tf32(float c[4], const unsigned a[4],
                                         unsigned b0, unsigned b1) {
    asm volatile(
        "mma.sync.aligned.m16n8k8.row.col.f32.tf32.tf32.f32 "
        "{%0,%1,%2,%3}, {%4,%5,%6,%7}, {%8,%9}, {%0,%1,%2,%3};\n"
        : "+f"(c[0]), "+f"(c[1]), "+f"(c[2]), "+f"(c[3])
        : "r"(a[0]), "r"(a[1]), "r"(a[2]), "r"(a[3]), "r"(b0), "r"(b1));
}

// ---------------------------------------------------------------------------
// 1. Input transpose: x (B, 512, 4096) -> X (B, 4096, 512)
// ---------------------------------------------------------------------------
__global__ void transpose_in_kernel(const float* __restrict__ x, float* __restrict__ X) {
    __shared__ float t[32][33];
    const int b  = blockIdx.z;
    const int p0 = blockIdx.x * 32;
    const int c0 = blockIdx.y * 32;
    const int tx = threadIdx.x, ty = threadIdx.y;
    #pragma unroll
    for (int i = ty; i < 32; i += 8)
        t[i][tx] = x[(b * 512 + c0 + i) * 4096 + p0 + tx];
    __syncthreads();
    #pragma unroll
    for (int i = ty; i < 32; i += 8)
        X[(b * 4096 + p0 + i) * 512 + c0 + tx] = t[tx][i];
}

// ---------------------------------------------------------------------------
// 2. 2x2 average pool
// ---------------------------------------------------------------------------
__global__ void pool_kernel(const float* __restrict__ X, float* __restrict__ pooled) {
    int idx = blockIdx.x * 256 + threadIdx.x;
    int c = idx & 511;
    int r = idx >> 9;
    int b = r >> 10;
    int g = r & 1023;
    int gh = g >> 5, gw = g & 31;
    long base = (long)(b * 4096 + gh * 128 + gw * 2) * 512 + c;
    float s = X[base] + X[base + 512] + X[base + 64 * 512] + X[base + 64 * 512 + 512];
    pooled[idx] = 0.25f * s;
}

// ---------------------------------------------------------------------------
// 3. tf32 GEMM: C[M,N] = A[M,K] @ B[K,N] (+bias).
//    Block 128x128, 8 warps (2x4), warp tile 64x32, k-chunk 32.
// ---------------------------------------------------------------------------
__global__ __launch_bounds__(256) void gemm_tf32(
    const float* __restrict__ A, const float* __restrict__ Bw,
    const float* __restrict__ bias, float* __restrict__ C,
    int M, int N, int K)
{
    __shared__ unsigned As[128 * 40];    // [m][k] pad 40
    __shared__ unsigned Bs[32 * 136];    // [k][n] pad 136

    const int tid = threadIdx.x;
    const int lane = tid & 31, w = tid >> 5;
    const int g = lane >> 2, t = lane & 3;
    const int wm = (w >> 2) * 64, wn = (w & 3) * 32;
    const int bn = blockIdx.x * 128, bm = blockIdx.y * 128;

    float c[4][4][4];
    #pragma unroll
    for (int mt = 0; mt < 4; mt++)
        #pragma unroll
        for (int nt = 0; nt < 4; nt++)
            #pragma unroll
            for (int i = 0; i < 4; i++) c[mt][nt][i] = 0.f;

    for (int k0 = 0; k0 < K; k0 += 32) {
        __syncthreads();
        #pragma unroll
        for (int i = 0; i < 4; i++) {
            int idx = tid + i * 256;
            int m = idx >> 3, kc = (idx & 7) * 4;
            float4 v = *(const float4*)(A + (long)(bm + m) * K + k0 + kc);
            *(uint4*)&As[m * 40 + kc] = f2tf4(v);
        }
        #pragma unroll
        for (int i = 0; i < 4; i++) {
            int idx = tid + i * 256;
            int kr = idx >> 5, nc = (idx & 31) * 4;
            float4 v = *(const float4*)(Bw + (long)(k0 + kr) * N + bn + nc);
            *(uint4*)&Bs[kr * 136 + nc] = f2tf4(v);
        }
        __syncthreads();

        #pragma unroll
        for (int ks = 0; ks < 4; ks++) {
            unsigned a[4][4], bf[4][2];
            #pragma unroll
            for (int mt = 0; mt < 4; mt++) {
                int r = wm + mt * 16 + g;
                a[mt][0] = As[r * 40 + ks * 8 + t];
                a[mt][1] = As[(r + 8) * 40 + ks * 8 + t];
                a[mt][2] = As[r * 40 + ks * 8 + t + 4];
                a[mt][3] = As[(r + 8) * 40 + ks * 8 + t + 4];
            }
            #pragma unroll
            for (int nt = 0; nt < 4; nt++) {
                bf[nt][0] = Bs[(ks * 8 + t) * 136 + wn + nt * 8 + g];
                bf[nt][1] = Bs[(ks * 8 + t + 4) * 136 + wn + nt * 8 + g];
            }
            #pragma unroll
            for (int mt = 0; mt < 4; mt++)
                #pragma unroll
                for (int nt = 0; nt < 4; nt++)
                    mma_tf32(c[mt][nt], a[mt], bf[nt][0], bf[nt][1]);
        }
    }

    float bv[4][2];
    #pragma unroll
    for (int nt = 0; nt < 4; nt++) {
        bv[nt][0] = bias ? bias[bn + wn + nt * 8 + 2 * t]     : 0.f;
        bv[nt][1] = bias ? bias[bn + wn + nt * 8 + 2 * t + 1] : 0.f;
    }

    #pragma unroll
    for (int mt = 0; mt < 4; mt++) {
        int row = bm + wm + mt * 16 + g;
        #pragma unroll
        for (int nt = 0; nt < 4; nt++) {
            int col = bn + wn + nt * 8 + 2 * t;
            float2 lo, hi;
            lo.x = c[mt][nt][0] + bv[nt][0]; lo.y = c[mt][nt][1] + bv[nt][1];
            hi.x = c[mt][nt][2] + bv[nt][0]; hi.y = c[mt][nt][3] + bv[nt][1];
            *(float2*)(C + (long)row * N + col)       = lo;
            *(float2*)(C + (long)(row + 8) * N + col) = hi;
        }
    }
}

// ---------------------------------------------------------------------------
// 4. Hi-fi windowed attention (fp32, tiny)
// ---------------------------------------------------------------------------
__global__ void hi_attn_kernel(const float* __restrict__ QKV, float* __restrict__ HiOut) {
    __shared__ float qk[4][768];
    __shared__ float sS[4][16];
    __shared__ float sP[4][16];

    const int tid = threadIdx.x;
    const int bg = blockIdx.x;
    const int b = bg >> 10;
    const int g = bg & 1023;
    const int gh = g >> 5, gw = g & 31;
    const int rowbase = b * 4096;

    for (int i = tid; i < 4 * 192; i += 256) {
        int n = i / 192;
        int c4 = (i % 192) * 4;
        int pix = (2 * gh + (n >> 1)) * 64 + 2 * gw + (n & 1);
        *(float4*)&qk[n][c4] = *(const float4*)(QKV + (long)(rowbase + pix) * 768 + c4);
    }
    __syncthreads();

    const int head = tid >> 6;
    const int r = tid & 63;

    if (r < 16) {
        int n = r >> 2, m = r & 3;
        const float* qp = &qk[n][head * 64];
        const float* kp = &qk[m][256 + head * 64];
        float a = 0.f;
        #pragma unroll
        for (int d = 0; d < 64; d++) a = fmaf(qp[d], kp[d], a);
        sS[head][r] = a * SCALE;
    }
    __syncthreads();

    if (r < 4) {
        int n = r;
        float mx = sS[head][n * 4];
        #pragma unroll
        for (int m = 1; m < 4; m++) mx = fmaxf(mx, sS[head][n * 4 + m]);
        float e[4], sum = 0.f;
        #pragma unroll
        for (int m = 0; m < 4; m++) { e[m] = __expf(sS[head][n * 4 + m] - mx); sum += e[m]; }
        float inv = 1.f / sum;
        #pragma unroll
        for (int m = 0; m < 4; m++) sP[head][n * 4 + m] = e[m] * inv;
    }
    __syncthreads();

    const int d = r;
    #pragma unroll
    for (int n = 0; n < 4; n++) {
        float o = 0.f;
        #pragma unroll
        for (int m = 0; m < 4; m++)
            o = fmaf(sP[head][n * 4 + m], qk[m][512 + head * 64 + d], o);
        int pix = (2 * gh + (n >> 1)) * 64 + 2 * gw + (n & 1);
        HiOut[(long)(rowbase + pix) * 256 + head * 64 + d] = o;
    }
}

// ---------------------------------------------------------------------------
// 5. Lo-fi flash attention, tf32 MMA.
//    Block = 128 threads (4 warps), 64 q-rows; 16 key tiles of 64.
//    Warp w owns q-rows [w*16, w*16+16). Q frags live in registers.
// ---------------------------------------------------------------------------
#define LOP 72
__global__ __launch_bounds__(128) void lo_attn_tf32(
    const float* __restrict__ Ql, const float* __restrict__ KVl,
    float* __restrict__ LoOut)
{
    extern __shared__ unsigned smu[];
    unsigned* Ps = smu;               // [64][LOP] : Q staging, then P
    unsigned* Ks = smu + 64 * LOP;    // [key][d]
    unsigned* Vs = smu + 2 * 64 * LOP;// [key][d]

    const int tid = threadIdx.x;
    const int lane = tid & 31, w = tid >> 5;
    const int g = lane >> 2, t = lane & 3;
    const int qt = blockIdx.x, h = blockIdx.y, b = blockIdx.z;

    const float* Qbase = Ql  + (long)(b * 4096 + qt * 64) * 256 + h * 64;
    const float* Kbase = KVl + (long)(b * 1024) * 512 + h * 64;

    // stage Q (scaled by SCALE*log2e), convert to tf32
    for (int idx = tid; idx < 64 * 16; idx += 128) {
        int q = idx >> 4, c4 = (idx & 15) * 4;
        float4 v = *(const float4*)(Qbase + (long)q * 256 + c4);
        v.x *= QSCALE; v.y *= QSCALE; v.z *= QSCALE; v.w *= QSCALE;
        *(uint4*)&Ps[q * LOP + c4] = f2tf4(v);
    }
    __syncthreads();

    const int r0 = w * 16 + g;
    unsigned Qa[8][4];
    #pragma unroll
    for (int kk = 0; kk < 8; kk++) {
        Qa[kk][0] = Ps[r0 * LOP + kk * 8 + t];
        Qa[kk][1] = Ps[(r0 + 8) * LOP + kk * 8 + t];
        Qa[kk][2] = Ps[r0 * LOP + kk * 8 + t + 4];
        Qa[kk][3] = Ps[(r0 + 8) * LOP + kk * 8 + t + 4];
    }

    float o[8][4];
    #pragma unroll
    for (int j = 0; j < 8; j++)
        #pragma unroll
        for (int i = 0; i < 4; i++) o[j][i] = 0.f;
    float m0 = -1e30f, m1 = -1e30f, l0 = 0.f, l1 = 0.f;

    for (int kt = 0; kt < 16; kt++) {
        __syncthreads();
        const float* Kt = Kbase + (long)(kt * 64) * 512;
        for (int idx = tid; idx < 64 * 16; idx += 128) {
            int key = idx >> 4, c4 = (idx & 15) * 4;
            const float* gp = Kt + (long)key * 512 + c4;
            float4 kv = *(const float4*)gp;
            float4 vv = *(const float4*)(gp + 256);
            *(uint4*)&Ks[key * LOP + c4] = f2tf4(kv);
            *(uint4*)&Vs[key * LOP + c4] = f2tf4(vv);
        }
        __syncthreads();

        // S = Q K^T : per thread 8 n-tiles x 4 regs
        float s[8][4];
        #pragma unroll
        for (int j = 0; j < 8; j++) {
            s[j][0] = s[j][1] = s[j][2] = s[j][3] = 0.f;
            #pragma unroll
            for (int kk = 0; kk < 8; kk++) {
                unsigned b0 = Ks[(j * 8 + g) * LOP + kk * 8 + t];
                unsigned b1 = Ks[(j * 8 + g) * LOP + kk * 8 + t + 4];
                mma_tf32(s[j], Qa[kk], b0, b1);
            }
        }

        // row-wise online softmax (rows r0 and r0+8); exp base-2 (scale folded)
        float mx0 = -1e30f, mx1 = -1e30f;
        #pragma unroll
        for (int j = 0; j < 8; j++) {
            mx0 = fmaxf(mx0, fmaxf(s[j][0], s[j][1]));
            mx1 = fmaxf(mx1, fmaxf(s[j][2], s[j][3]));
        }
        mx0 = fmaxf(mx0, __shfl_xor_sync(0xffffffffu, mx0, 1));
        mx0 = fmaxf(mx0, __shfl_xor_sync(0xffffffffu, mx0, 2));
        mx1 = fmaxf(mx1, __shfl_xor_sync(0xffffffffu, mx1, 1));
        mx1 = fmaxf(mx1, __shfl_xor_sync(0xffffffffu, mx1, 2));
        float nm0 = fmaxf(m0, mx0), nm1 = fmaxf(m1, mx1);
        float a0 = ex2(m0 - nm0), a1 = ex2(m1 - nm1);
        float rs0 = 0.f, rs1 = 0.f;
        #pragma unroll
        for (int j = 0; j < 8; j++) {
            s[j][0] = ex2(s[j][0] - nm0); rs0 += s[j][0];
            s[j][1] = ex2(s[j][1] - nm0); rs0 += s[j][1];
            s[j][2] = ex2(s[j][2] - nm1); rs1 += s[j][2];
            s[j][3] = ex2(s[j][3] - nm1); rs1 += s[j][3];
        }
        rs0 += __shfl_xor_sync(0xffffffffu, rs0, 1);
        rs0 += __shfl_xor_sync(0xffffffffu, rs0, 2);
        rs1 += __shfl_xor_sync(0xffffffffu, rs1, 1);
        rs1 += __shfl_xor_sync(0xffffffffu, rs1, 2);
        l0 = l0 * a0 + rs0; m0 = nm0;
        l1 = l1 * a1 + rs1; m1 = nm1;
        #pragma unroll
        for (int j = 0; j < 8; j++) {
            o[j][0] *= a0; o[j][1] *= a0;
            o[j][2] *= a1; o[j][3] *= a1;
        }

        // store P (tf32) — each warp writes only its own 16 rows
        #pragma unroll
        for (int j = 0; j < 8; j++) {
            uint2 p0; p0.x = f2tf(s[j][0]); p0.y = f2tf(s[j][1]);
            uint2 p1; p1.x = f2tf(s[j][2]); p1.y = f2tf(s[j][3]);
            *(uint2*)&Ps[r0 * LOP + j * 8 + 2 * t]       = p0;
            *(uint2*)&Ps[(r0 + 8) * LOP + j * 8 + 2 * t] = p1;
        }
        __syncwarp();

        // O += P @ V
        #pragma unroll
        for (int kk = 0; kk < 8; kk++) {
            unsigned pa[4];
            pa[0] = Ps[r0 * LOP + kk * 8 + t];
            pa[1] = Ps[(r0 + 8) * LOP + kk * 8 + t];
            pa[2] = Ps[r0 * LOP + kk * 8 + t + 4];
            pa[3] = Ps[(r0 + 8) * LOP + kk * 8 + t + 4];
            #pragma unroll
            for (int j = 0; j < 8; j++) {
                unsigned b0 = Vs[(kk * 8 + t) * LOP + j * 8 + g];
                unsigned b1 = Vs[(kk * 8 + t + 4) * LOP + j * 8 + g];
                mma_tf32(o[j], pa, b0, b1);
            }
        }
    }

    float inv0 = 1.f / l0, inv1 = 1.f / l1;
    long row = (long)(b * 4096 + qt * 64) + r0;
    #pragma unroll
    for (int j = 0; j < 8; j++) {
        int col = h * 64 + j * 8 + 2 * t;
        float2 x0; x0.x = o[j][0] * inv0; x0.y = o[j][1] * inv0;
        float2 x1; x1.x = o[j][2] * inv1; x1.y = o[j][3] * inv1;
        *(float2*)(LoOut + row * 256 + col)       = x0;
        *(float2*)(LoOut + (row + 8) * 256 + col) = x1;
    }
}

// ---------------------------------------------------------------------------
// 6. Concat + transpose to NCHW
// ---------------------------------------------------------------------------
__global__ void concat_transpose_kernel(const float* __restrict__ HiFi,
                                        const float* __restrict__ LoFi,
                                        float* __restrict__ out)
{
    __shared__ float t[32][33];
    const int z = blockIdx.z;
    const int b = z >> 1;
    const float* src = (z & 1) ? LoFi : HiFi;
    const int coff = (z & 1) * 256;
    const int p0 = blockIdx.x * 32;
    const int c0 = blockIdx.y * 32;
    const int tx = threadIdx.x, ty = threadIdx.y;
    #pragma unroll
    for (int i = ty; i < 32; i += 8)
        t[i][tx] = src[(long)(b * 4096 + p0 + i) * 256 + c0 + tx];
    __syncthreads();
    #pragma unroll
    for (int i = ty; i < 32; i += 8)
        out[(long)(b * 512 + coff + c0 + i) * 4096 + p0 + tx] = t[tx][i];
}

// ---------------------------------------------------------------------------
// Launch
// ---------------------------------------------------------------------------
extern "C" void kernel_launch(void* const* d_in, const int* in_sizes, int n_in,
                              void* d_out, int out_size)
{
    const float* x        = (const float*)d_in[0];
    const float* h_qkv_w  = (const float*)d_in[1];
    const float* h_proj_w = (const float*)d_in[2];
    const float* h_proj_b = (const float*)d_in[3];
    const float* l_q_w    = (const float*)d_in[4];
    const float* l_kv_w   = (const float*)d_in[5];
    const float* l_proj_w = (const float*)d_in[6];
    const float* l_proj_b = (const float*)d_in[7];
    float* out = (float*)d_out;

    float *X, *P, *QKV, *Ql, *KVl, *HiO, *LoO, *HiF, *LoF;
    cudaGetSymbolAddress((void**)&X,   g_X);
    cudaGetSymbolAddress((void**)&P,   g_pooled);
    cudaGetSymbolAddress((void**)&QKV, g_QKV);
    cudaGetSymbolAddress((void**)&Ql,  g_Ql);
    cudaGetSymbolAddress((void**)&KVl, g_KVl);
    cudaGetSymbolAddress((void**)&HiO, g_HiOut);
    cudaGetSymbolAddress((void**)&LoO, g_LoOut);
    cudaGetSymbolAddress((void**)&HiF, g_HiFi);
    cudaGetSymbolAddress((void**)&LoF, g_LoFi);

    transpose_in_kernel<<<dim3(128, 16, 4), dim3(32, 8)>>>(x, X);
    pool_kernel<<<8192, 256>>>(X, P);

    gemm_tf32<<<dim3(6, 128), 256>>>(X, h_qkv_w, nullptr, QKV, BHW, 768, 512);
    gemm_tf32<<<dim3(2, 128), 256>>>(X, l_q_w,   nullptr, Ql,  BHW, 256, 512);
    gemm_tf32<<<dim3(4, 32),  256>>>(P, l_kv_w,  nullptr, KVl, BG,  512, 512);

    hi_attn_kernel<<<4096, 256>>>(QKV, HiO);

    cudaFuncSetAttribute(lo_attn_tf32, cudaFuncAttributeMaxDynamicSharedMemorySize,
                         3 * 64 * LOP * (int)sizeof(unsigned));
    lo_attn_tf32<<<dim3(64, 4, 4), 128, 3 * 64 * LOP * sizeof(unsigned)>>>(Ql, KVl, LoO);

    gemm_tf32<<<dim3(2, 128), 256>>>(HiO, h_proj_w, h_proj_b, HiF, BHW, 256, 256);
    gemm_tf32<<<dim3(2, 128), 256>>>(LoO, l_proj_w, l_proj_b, LoF, BHW, 256, 256);

    concat_transpose_kernel<<<dim3(128, 8, 8), dim3(32, 8)>>>(HiF, LoF, out);
}

// round 14
// speedup vs baseline: 1.1135x; 1.1135x over previous
#include <cuda_runtime.h>

// ---------------------------------------------------------------------------
// HiLo attention, tf32 tensor-core version, cp.async pipelined.
// Shapes: B=4, C=512, H=W=64 (HW=4096, BHW=16384), heads 4+4, head_dim 64.
// ---------------------------------------------------------------------------

#define BATCH   4
#define CDIM    512
#define BHW     16384
#define BG      4096
#define SCALE   0.125f                 // 64^-0.5
#define QSCALE  0.18033688f            // SCALE * log2(e)

// Weight scratch offsets (tf32-rounded copies)
#define W_QKV   0
#define W_Q     393216
#define W_KV    524288
#define W_HP    786432
#define W_LP    851968
#define W_TOT   917504

// Scratch
__device__ float g_X[BHW * CDIM];
__device__ float g_pooled[BG * CDIM];
__device__ float g_W[W_TOT];
__device__ float g_QKV[BHW * 768];
__device__ float g_Ql[BHW * 256];
__device__ float g_KVl[BG * 512];
__device__ float g_HiOut[BHW * 256];
__device__ float g_LoOut[BHW * 256];

// ---------------------------------------------------------------------------
// helpers
// ---------------------------------------------------------------------------
__device__ __forceinline__ unsigned f2tf(float f) {
    unsigned u;
    asm("cvt.rna.tf32.f32 %0, %1;" : "=r"(u) : "f"(f));
    return u;
}
__device__ __forceinline__ uint4 f2tf4(float4 v) {
    uint4 u;
    u.x = f2tf(v.x); u.y = f2tf(v.y); u.z = f2tf(v.z); u.w = f2tf(v.w);
    return u;
}
__device__ __forceinline__ float ex2(float x) {
    float r;
    asm("ex2.approx.ftz.f32 %0, %1;" : "=f"(r) : "f"(x));
    return r;
}
__device__ __forceinline__ void mma_tf32(float c[4], const unsigned a[4],
                                         unsigned b0, unsigned b1) {
    asm volatile(
        "mma.sync.aligned.m16n8k8.row.col.f32.tf32.tf32.f32 "
        "{%0,%1,%2,%3}, {%4,%5,%6,%7}, {%8,%9}, {%0,%1,%2,%3};\n"
        : "+f"(c[0]), "+f"(c[1]), "+f"(c[2]), "+f"(c[3])
        : "r"(a[0]), "r"(a[1]), "r"(a[2]), "r"(a[3]), "r"(b0), "r"(b1));
}
__device__ __forceinline__ void cp16(void* dst, const void* src) {
    unsigned d = (unsigned)__cvta_generic_to_shared(dst);
    asm volatile("cp.async.cg.shared.global [%0], [%1], 16;\n" :: "r"(d), "l"(src));
}
#define CP_COMMIT() asm volatile("cp.async.commit_group;\n" ::: "memory")
#define CP_WAIT0()  asm volatile("cp.async.wait_group 0;\n" ::: "memory")
#define CP_WAIT1()  asm volatile("cp.async.wait_group 1;\n" ::: "memory")

// ---------------------------------------------------------------------------
// 0. Round all weights to tf32 into g_W
// ---------------------------------------------------------------------------
__global__ void convert_w_kernel(const float* __restrict__ qkv, const float* __restrict__ q,
                                 const float* __restrict__ kv, const float* __restrict__ hp,
                                 const float* __restrict__ lp, float* __restrict__ W) {
    int i4 = (blockIdx.x * 256 + threadIdx.x) * 4;
    const float* src; int off;
    if      (i4 < W_Q)  { src = qkv; off = W_QKV; }
    else if (i4 < W_KV) { src = q;   off = W_Q;   }
    else if (i4 < W_HP) { src = kv;  off = W_KV;  }
    else if (i4 < W_LP) { src = hp;  off = W_HP;  }
    else                { src = lp;  off = W_LP;  }
    float4 v = *(const float4*)(src + (i4 - off));
    *(uint4*)(W + i4) = f2tf4(v);
}

// ---------------------------------------------------------------------------
// 1. Input transpose: x (B, 512, 4096) -> X (B, 4096, 512), tf32-rounded
// ---------------------------------------------------------------------------
__global__ void transpose_in_kernel(const float* __restrict__ x, float* __restrict__ X) {
    __shared__ float t[32][33];
    const int b  = blockIdx.z;
    const int p0 = blockIdx.x * 32;
    const int c0 = blockIdx.y * 32;
    const int tx = threadIdx.x, ty = threadIdx.y;
    #pragma unroll
    for (int i = ty; i < 32; i += 8)
        t[i][tx] = x[(b * 512 + c0 + i) * 4096 + p0 + tx];
    __syncthreads();
    #pragma unroll
    for (int i = ty; i < 32; i += 8)
        X[(b * 4096 + p0 + i) * 512 + c0 + tx] = __uint_as_float(f2tf(t[tx][i]));
}

// ---------------------------------------------------------------------------
// 2. 2x2 average pool (output tf32-rounded)
// ---------------------------------------------------------------------------
__global__ void pool_kernel(const float* __restrict__ X, float* __restrict__ pooled) {
    int idx = blockIdx.x * 256 + threadIdx.x;
    int c = idx & 511;
    int r = idx >> 9;
    int b = r >> 10;
    int g = r & 1023;
    int gh = g >> 5, gw = g & 31;
    long base = (long)(b * 4096 + gh * 128 + gw * 2) * 512 + c;
    float s = X[base] + X[base + 512] + X[base + 64 * 512] + X[base + 64 * 512 + 512];
    pooled[idx] = __uint_as_float(f2tf(0.25f * s));
}

// ---------------------------------------------------------------------------
// 3. tf32 GEMM, cp.async 2-stage pipeline. Inputs must be tf32-rounded floats.
//    Block 128x128, 8 warps (2x4), warp tile 64x32, k-chunk 32.
//    mode 0: plain store; mode 1: tf32-rounded store;
//    mode 2: bias + transposed NCHW store into out at channel offset coff.
// ---------------------------------------------------------------------------
#define AS_SZ (128 * 40)
#define BS_SZ (32 * 136)
#define GEMM_SMEM (2 * (AS_SZ + BS_SZ) * 4)   // 75776 bytes

__global__ __launch_bounds__(256) void gemm_tf32(
    const float* __restrict__ A, const float* __restrict__ Bw,
    const float* __restrict__ bias, float* __restrict__ C,
    int M, int N, int K, int mode, int coff)
{
    extern __shared__ unsigned sh[];

    const int tid = threadIdx.x;
    const int lane = tid & 31, w = tid >> 5;
    const int g = lane >> 2, t = lane & 3;
    const int wm = (w >> 2) * 64, wn = (w & 3) * 32;
    const int bn = blockIdx.x * 128, bm = blockIdx.y * 128;

    float c[4][4][4];
    #pragma unroll
    for (int mt = 0; mt < 4; mt++)
        #pragma unroll
        for (int nt = 0; nt < 4; nt++)
            #pragma unroll
            for (int i = 0; i < 4; i++) c[mt][nt][i] = 0.f;

    // prologue: stage 0
    {
        unsigned* As = sh;
        unsigned* Bs = sh + AS_SZ;
        #pragma unroll
        for (int i = 0; i < 4; i++) {
            int idx = tid + i * 256;
            int m = idx >> 3, kc = (idx & 7) * 4;
            cp16(&As[m * 40 + kc], A + (long)(bm + m) * K + kc);
        }
        #pragma unroll
        for (int i = 0; i < 4; i++) {
            int idx = tid + i * 256;
            int kr = idx >> 5, nc = (idx & 31) * 4;
            cp16(&Bs[kr * 136 + nc], Bw + (long)kr * N + bn + nc);
        }
        CP_COMMIT();
    }

    const int NK = K >> 5;
    for (int kc = 0; kc < NK; kc++) {
        if (kc + 1 < NK) {
            int k0 = (kc + 1) * 32;
            unsigned* As = sh + ((kc + 1) & 1) * (AS_SZ + BS_SZ);
            unsigned* Bs = As + AS_SZ;
            #pragma unroll
            for (int i = 0; i < 4; i++) {
                int idx = tid + i * 256;
                int m = idx >> 3, kcc = (idx & 7) * 4;
                cp16(&As[m * 40 + kcc], A + (long)(bm + m) * K + k0 + kcc);
            }
            #pragma unroll
            for (int i = 0; i < 4; i++) {
                int idx = tid + i * 256;
                int kr = idx >> 5, nc = (idx & 31) * 4;
                cp16(&Bs[kr * 136 + nc], Bw + (long)(k0 + kr) * N + bn + nc);
            }
            CP_COMMIT();
            CP_WAIT1();
        } else {
            CP_WAIT0();
        }
        __syncthreads();

        unsigned* As = sh + (kc & 1) * (AS_SZ + BS_SZ);
        unsigned* Bs = As + AS_SZ;
        #pragma unroll
        for (int ks = 0; ks < 4; ks++) {
            unsigned a[4][4], bf[4][2];
            #pragma unroll
            for (int mt = 0; mt < 4; mt++) {
                int r = wm + mt * 16 + g;
                a[mt][0] = As[r * 40 + ks * 8 + t];
                a[mt][1] = As[(r + 8) * 40 + ks * 8 + t];
                a[mt][2] = As[r * 40 + ks * 8 + t + 4];
                a[mt][3] = As[(r + 8) * 40 + ks * 8 + t + 4];
            }
            #pragma unroll
            for (int nt = 0; nt < 4; nt++) {
                bf[nt][0] = Bs[(ks * 8 + t) * 136 + wn + nt * 8 + g];
                bf[nt][1] = Bs[(ks * 8 + t + 4) * 136 + wn + nt * 8 + g];
            }
            #pragma unroll
            for (int mt = 0; mt < 4; mt++)
                #pragma unroll
                for (int nt = 0; nt < 4; nt++)
                    mma_tf32(c[mt][nt], a[mt], bf[nt][0], bf[nt][1]);
        }
        __syncthreads();
    }

    if (mode == 2) {
        // bias + transposed NCHW store: out[(b*512 + coff + bn + col)*4096 + pix]
        float* S = (float*)sh;     // [128 cols][132]
        #pragma unroll
        for (int nt = 0; nt < 4; nt++) {
            int col = wn + nt * 8 + 2 * t;
            float b0 = bias[bn + col], b1 = bias[bn + col + 1];
            #pragma unroll
            for (int mt = 0; mt < 4; mt++) {
                int r = wm + mt * 16 + g;
                S[col * 132 + r]           = c[mt][nt][0] + b0;
                S[(col + 1) * 132 + r]     = c[mt][nt][1] + b1;
                S[col * 132 + r + 8]       = c[mt][nt][2] + b0;
                S[(col + 1) * 132 + r + 8] = c[mt][nt][3] + b1;
            }
        }
        __syncthreads();
        const int b = bm >> 12;
        const int pix0 = bm & 4095;
        #pragma unroll
        for (int i = 0; i < 16; i++) {
            int idx = tid + i * 256;
            int cch = idx >> 5, p4 = (idx & 31) * 4;
            float4 v = *(const float4*)&S[cch * 132 + p4];
            *(float4*)(C + (long)(b * 512 + coff + bn + cch) * 4096 + pix0 + p4) = v;
        }
        return;
    }

    float bv[4][2];
    #pragma unroll
    for (int nt = 0; nt < 4; nt++) {
        bv[nt][0] = bias ? bias[bn + wn + nt * 8 + 2 * t]     : 0.f;
        bv[nt][1] = bias ? bias[bn + wn + nt * 8 + 2 * t + 1] : 0.f;
    }
    #pragma unroll
    for (int mt = 0; mt < 4; mt++) {
        int row = bm + wm + mt * 16 + g;
        #pragma unroll
        for (int nt = 0; nt < 4; nt++) {
            int col = bn + wn + nt * 8 + 2 * t;
            float2 lo, hi;
            lo.x = c[mt][nt][0] + bv[nt][0]; lo.y = c[mt][nt][1] + bv[nt][1];
            hi.x = c[mt][nt][2] + bv[nt][0]; hi.y = c[mt][nt][3] + bv[nt][1];
            if (mode == 1) {
                lo.x = __uint_as_float(f2tf(lo.x)); lo.y = __uint_as_float(f2tf(lo.y));
                hi.x = __uint_as_float(f2tf(hi.x)); hi.y = __uint_as_float(f2tf(hi.y));
            }
            *(float2*)(C + (long)row * N + col)       = lo;
            *(float2*)(C + (long)(row + 8) * N + col) = hi;
        }
    }
}

// ---------------------------------------------------------------------------
// 4. Hi-fi windowed attention (fp32, tiny). Output tf32-rounded.
// ---------------------------------------------------------------------------
__global__ void hi_attn_kernel(const float* __restrict__ QKV, float* __restrict__ HiOut) {
    __shared__ float qk[4][768];
    __shared__ float sS[4][16];
    __shared__ float sP[4][16];

    const int tid = threadIdx.x;
    const int bg = blockIdx.x;
    const int b = bg >> 10;
    const int g = bg & 1023;
    const int gh = g >> 5, gw = g & 31;
    const int rowbase = b * 4096;

    for (int i = tid; i < 4 * 192; i += 256) {
        int n = i / 192;
        int c4 = (i % 192) * 4;
        int pix = (2 * gh + (n >> 1)) * 64 + 2 * gw + (n & 1);
        *(float4*)&qk[n][c4] = *(const float4*)(QKV + (long)(rowbase + pix) * 768 + c4);
    }
    __syncthreads();

    const int head = tid >> 6;
    const int r = tid & 63;

    if (r < 16) {
        int n = r >> 2, m = r & 3;
        const float* qp = &qk[n][head * 64];
        const float* kp = &qk[m][256 + head * 64];
        float a = 0.f;
        #pragma unroll
        for (int d = 0; d < 64; d++) a = fmaf(qp[d], kp[d], a);
        sS[head][r] = a * SCALE;
    }
    __syncthreads();

    if (r < 4) {
        int n = r;
        float mx = sS[head][n * 4];
        #pragma unroll
        for (int m = 1; m < 4; m++) mx = fmaxf(mx, sS[head][n * 4 + m]);
        float e[4], sum = 0.f;
        #pragma unroll
        for (int m = 0; m < 4; m++) { e[m] = __expf(sS[head][n * 4 + m] - mx); sum += e[m]; }
        float inv = 1.f / sum;
        #pragma unroll
        for (int m = 0; m < 4; m++) sP[head][n * 4 + m] = e[m] * inv;
    }
    __syncthreads();

    const int d = r;
    #pragma unroll
    for (int n = 0; n < 4; n++) {
        float o = 0.f;
        #pragma unroll
        for (int m = 0; m < 4; m++)
            o = fmaf(sP[head][n * 4 + m], qk[m][512 + head * 64 + d], o);
        int pix = (2 * gh + (n >> 1)) * 64 + 2 * gw + (n & 1);
        HiOut[(long)(rowbase + pix) * 256 + head * 64 + d] = __uint_as_float(f2tf(o));
    }
}

// ---------------------------------------------------------------------------
// 5. Lo-fi flash attention, tf32 MMA. 256 threads (8 warps), 128 q-rows/block;
//    16 key tiles of 64. KV pre-rounded -> raw cp.async staging.
// ---------------------------------------------------------------------------
#define LOP 72
#define LO_SMEM ((128 * LOP + 2 * 64 * LOP) * 4)   // 73728 bytes

__global__ __launch_bounds__(256) void lo_attn_tf32(
    const float* __restrict__ Ql, const float* __restrict__ KVl,
    float* __restrict__ LoOut)
{
    extern __shared__ unsigned smu[];
    unsigned* Ps = smu;                 // [128][LOP] : Q staging, then P
    unsigned* Ks = smu + 128 * LOP;     // [64][LOP]
    unsigned* Vs = smu + (128 + 64) * LOP;

    const int tid = threadIdx.x;
    const int lane = tid & 31, w = tid >> 5;
    const int g = lane >> 2, t = lane & 3;
    const int qt = blockIdx.x, h = blockIdx.y, b = blockIdx.z;

    const float* Qbase = Ql  + (long)(b * 4096 + qt * 128) * 256 + h * 64;
    const float* Kbase = KVl + (long)(b * 1024) * 512 + h * 64;

    // stage Q (scaled by SCALE*log2e), round to tf32
    for (int idx = tid; idx < 128 * 16; idx += 256) {
        int q = idx >> 4, c4 = (idx & 15) * 4;
        float4 v = *(const float4*)(Qbase + (long)q * 256 + c4);
        v.x *= QSCALE; v.y *= QSCALE; v.z *= QSCALE; v.w *= QSCALE;
        *(uint4*)&Ps[q * LOP + c4] = f2tf4(v);
    }
    __syncthreads();

    const int r0 = w * 16 + g;
    unsigned Qa[8][4];
    #pragma unroll
    for (int kk = 0; kk < 8; kk++) {
        Qa[kk][0] = Ps[r0 * LOP + kk * 8 + t];
        Qa[kk][1] = Ps[(r0 + 8) * LOP + kk * 8 + t];
        Qa[kk][2] = Ps[r0 * LOP + kk * 8 + t + 4];
        Qa[kk][3] = Ps[(r0 + 8) * LOP + kk * 8 + t + 4];
    }

    float o[8][4];
    #pragma unroll
    for (int j = 0; j < 8; j++)
        #pragma unroll
        for (int i = 0; i < 4; i++) o[j][i] = 0.f;
    float m0 = -1e30f, m1 = -1e30f, l0 = 0.f, l1 = 0.f;

    for (int kt = 0; kt < 16; kt++) {
        __syncthreads();
        const float* Kt = Kbase + (long)(kt * 64) * 512;
        #pragma unroll
        for (int i = 0; i < 4; i++) {
            int idx = tid + i * 256;
            int key = idx >> 4, c4 = (idx & 15) * 4;
            const float* gp = Kt + (long)key * 512 + c4;
            cp16(&Ks[key * LOP + c4], gp);
            cp16(&Vs[key * LOP + c4], gp + 256);
        }
        CP_COMMIT();
        CP_WAIT0();
        __syncthreads();

        // S = Q K^T : per thread 8 n-tiles x 4 regs
        float s[8][4];
        #pragma unroll
        for (int j = 0; j < 8; j++) {
            s[j][0] = s[j][1] = s[j][2] = s[j][3] = 0.f;
            #pragma unroll
            for (int kk = 0; kk < 8; kk++) {
                unsigned b0 = Ks[(j * 8 + g) * LOP + kk * 8 + t];
                unsigned b1 = Ks[(j * 8 + g) * LOP + kk * 8 + t + 4];
                mma_tf32(s[j], Qa[kk], b0, b1);
            }
        }

        // online softmax (rows r0, r0+8); base-2 exp (scale folded into Q)
        float mx0 = -1e30f, mx1 = -1e30f;
        #pragma unroll
        for (int j = 0; j < 8; j++) {
            mx0 = fmaxf(mx0, fmaxf(s[j][0], s[j][1]));
            mx1 = fmaxf(mx1, fmaxf(s[j][2], s[j][3]));
        }
        mx0 = fmaxf(mx0, __shfl_xor_sync(0xffffffffu, mx0, 1));
        mx0 = fmaxf(mx0, __shfl_xor_sync(0xffffffffu, mx0, 2));
        mx1 = fmaxf(mx1, __shfl_xor_sync(0xffffffffu, mx1, 1));
        mx1 = fmaxf(mx1, __shfl_xor_sync(0xffffffffu, mx1, 2));
        float nm0 = fmaxf(m0, mx0), nm1 = fmaxf(m1, mx1);
        float a0 = ex2(m0 - nm0), a1 = ex2(m1 - nm1);
        float rs0 = 0.f, rs1 = 0.f;
        #pragma unroll
        for (int j = 0; j < 8; j++) {
            s[j][0] = ex2(s[j][0] - nm0); rs0 += s[j][0];
            s[j][1] = ex2(s[j][1] - nm0); rs0 += s[j][1];
            s[j][2] = ex2(s[j][2] - nm1); rs1 += s[j][2];
            s[j][3] = ex2(s[j][3] - nm1); rs1 += s[j][3];
        }
        rs0 += __shfl_xor_sync(0xffffffffu, rs0, 1);
        rs0 += __shfl_xor_sync(0xffffffffu, rs0, 2);
        rs1 += __shfl_xor_sync(0xffffffffu, rs1, 1);
        rs1 += __shfl_xor_sync(0xffffffffu, rs1, 2);
        l0 = l0 * a0 + rs0; m0 = nm0;
        l1 = l1 * a1 + rs1; m1 = nm1;
        #pragma unroll
        for (int j = 0; j < 8; j++) {
            o[j][0] *= a0; o[j][1] *= a0;
            o[j][2] *= a1; o[j][3] *= a1;
        }

        // store P (tf32) — each warp writes only its own 16 rows
        #pragma unroll
        for (int j = 0; j < 8; j++) {
            uint2 p0; p0.x = f2tf(s[j][0]); p0.y = f2tf(s[j][1]);
            uint2 p1; p1.x = f2tf(s[j][2]); p1.y = f2tf(s[j][3]);
            *(uint2*)&Ps[r0 * LOP + j * 8 + 2 * t]       = p0;
            *(uint2*)&Ps[(r0 + 8) * LOP + j * 8 + 2 * t] = p1;
        }
        __syncwarp();

        // O += P @ V
        #pragma unroll
        for (int kk = 0; kk < 8; kk++) {
            unsigned pa[4];
            pa[0] = Ps[r0 * LOP + kk * 8 + t];
            pa[1] = Ps[(r0 + 8) * LOP + kk * 8 + t];
            pa[2] = Ps[r0 * LOP + kk * 8 + t + 4];
            pa[3] = Ps[(r0 + 8) * LOP + kk * 8 + t + 4];
            #pragma unroll
            for (int j = 0; j < 8; j++) {
                unsigned b0 = Vs[(kk * 8 + t) * LOP + j * 8 + g];
                unsigned b1 = Vs[(kk * 8 + t + 4) * LOP + j * 8 + g];
                mma_tf32(o[j], pa, b0, b1);
            }
        }
    }

    // write normalized, tf32-rounded output (feeds proj GEMM)
    float inv0 = 1.f / l0, inv1 = 1.f / l1;
    long row = (long)(b * 4096 + qt * 128) + r0;
    #pragma unroll
    for (int j = 0; j < 8; j++) {
        int col = h * 64 + j * 8 + 2 * t;
        uint2 x0; x0.x = f2tf(o[j][0] * inv0); x0.y = f2tf(o[j][1] * inv0);
        uint2 x1; x1.x = f2tf(o[j][2] * inv1); x1.y = f2tf(o[j][3] * inv1);
        *(uint2*)(LoOut + row * 256 + col)       = x0;
        *(uint2*)(LoOut + (row + 8) * 256 + col) = x1;
    }
}

// ---------------------------------------------------------------------------
// Launch
// ---------------------------------------------------------------------------
extern "C" void kernel_launch(void* const* d_in, const int* in_sizes, int n_in,
                              void* d_out, int out_size)
{
    const float* x        = (const float*)d_in[0];
    const float* h_qkv_w  = (const float*)d_in[1];
    const float* h_proj_w = (const float*)d_in[2];
    const float* h_proj_b = (const float*)d_in[3];
    const float* l_q_w    = (const float*)d_in[4];
    const float* l_kv_w   = (const float*)d_in[5];
    const float* l_proj_w = (const float*)d_in[6];
    const float* l_proj_b = (const float*)d_in[7];
    float* out = (float*)d_out;

    float *X, *P, *W, *QKV, *Ql, *KVl, *HiO, *LoO;
    cudaGetSymbolAddress((void**)&X,   g_X);
    cudaGetSymbolAddress((void**)&P,   g_pooled);
    cudaGetSymbolAddress((void**)&W,   g_W);
    cudaGetSymbolAddress((void**)&QKV, g_QKV);
    cudaGetSymbolAddress((void**)&Ql,  g_Ql);
    cudaGetSymbolAddress((void**)&KVl, g_KVl);
    cudaGetSymbolAddress((void**)&HiO, g_HiOut);
    cudaGetSymbolAddress((void**)&LoO, g_LoOut);

    cudaFuncSetAttribute(gemm_tf32, cudaFuncAttributeMaxDynamicSharedMemorySize, GEMM_SMEM);
    cudaFuncSetAttribute(lo_attn_tf32, cudaFuncAttributeMaxDynamicSharedMemorySize, LO_SMEM);

    convert_w_kernel<<<W_TOT / 1024, 256>>>(h_qkv_w, l_q_w, l_kv_w, h_proj_w, l_proj_w, W);
    transpose_in_kernel<<<dim3(128, 16, 4), dim3(32, 8)>>>(x, X);
    pool_kernel<<<8192, 256>>>(X, P);

    gemm_tf32<<<dim3(6, 128), 256, GEMM_SMEM>>>(X, W + W_QKV, nullptr, QKV, BHW, 768, 512, 0, 0);
    gemm_tf32<<<dim3(2, 128), 256, GEMM_SMEM>>>(X, W + W_Q,   nullptr, Ql,  BHW, 256, 512, 0, 0);
    gemm_tf32<<<dim3(4, 32),  256, GEMM_SMEM>>>(P, W + W_KV,  nullptr, KVl, BG,  512, 512, 1, 0);

    hi_attn_kernel<<<4096, 256>>>(QKV, HiO);
    lo_attn_tf32<<<dim3(32, 4, 4), 256, LO_SMEM>>>(Ql, KVl, LoO);

    // proj GEMMs write transposed NCHW directly into the output (concat fused)
    gemm_tf32<<<dim3(2, 128), 256, GEMM_SMEM>>>(HiO, W + W_HP, h_proj_b, out, BHW, 256, 256, 2, 0);
    gemm_tf32<<<dim3(2, 128), 256, GEMM_SMEM>>>(LoO, W + W_LP, l_proj_b, out, BHW, 256, 256, 2, 256);
}

// round 15
// speedup vs baseline: 1.1171x; 1.0032x over previous
#include <cuda_runtime.h>

// ---------------------------------------------------------------------------
// HiLo attention, tf32 tensor-core version, cp.async pipelined.
// Shapes: B=4, C=512, H=W=64 (HW=4096, BHW=16384), heads 4+4, head_dim 64.
// ---------------------------------------------------------------------------

#define BATCH   4
#define CDIM    512
#define BHW     16384
#define BG      4096
#define SCALE   0.125f                 // 64^-0.5
#define QSCALE  0.18033688f            // SCALE * log2(e)

// Weight scratch offsets (tf32-rounded copies)
#define W_QKV   0
#define W_Q     393216
#define W_KV    524288
#define W_HP    786432
#define W_LP    851968
#define W_TOT   917504

// Scratch
__device__ float g_X[BHW * CDIM];
__device__ float g_pooled[BG * CDIM];
__device__ float g_W[W_TOT];
__device__ float g_QKV[BHW * 768];
__device__ float g_Ql[BHW * 256];
__device__ float g_KVl[BG * 512];
__device__ float g_HiOut[BHW * 256];
__device__ float g_LoOut[BHW * 256];

// ---------------------------------------------------------------------------
// helpers
// ---------------------------------------------------------------------------
__device__ __forceinline__ unsigned f2tf(float f) {
    unsigned u;
    asm("cvt.rna.tf32.f32 %0, %1;" : "=r"(u) : "f"(f));
    return u;
}
__device__ __forceinline__ uint4 f2tf4(float4 v) {
    uint4 u;
    u.x = f2tf(v.x); u.y = f2tf(v.y); u.z = f2tf(v.z); u.w = f2tf(v.w);
    return u;
}
__device__ __forceinline__ float ex2(float x) {
    float r;
    asm("ex2.approx.ftz.f32 %0, %1;" : "=f"(r) : "f"(x));
    return r;
}
__device__ __forceinline__ void mma_tf32(float c[4], const unsigned a[4],
                                         unsigned b0, unsigned b1) {
    asm volatile(
        "mma.sync.aligned.m16n8k8.row.col.f32.tf32.tf32.f32 "
        "{%0,%1,%2,%3}, {%4,%5,%6,%7}, {%8,%9}, {%0,%1,%2,%3};\n"
        : "+f"(c[0]), "+f"(c[1]), "+f"(c[2]), "+f"(c[3])
        : "r"(a[0]), "r"(a[1]), "r"(a[2]), "r"(a[3]), "r"(b0), "r"(b1));
}
__device__ __forceinline__ void cp16(void* dst, const void* src) {
    unsigned d = (unsigned)__cvta_generic_to_shared(dst);
    asm volatile("cp.async.cg.shared.global [%0], [%1], 16;\n" :: "r"(d), "l"(src));
}
#define CP_COMMIT() asm volatile("cp.async.commit_group;\n" ::: "memory")
#define CP_WAIT0()  asm volatile("cp.async.wait_group 0;\n" ::: "memory")
#define CP_WAIT1()  asm volatile("cp.async.wait_group 1;\n" ::: "memory")

// ---------------------------------------------------------------------------
// 0. Round all weights to tf32 into g_W
// ---------------------------------------------------------------------------
__global__ void convert_w_kernel(const float* __restrict__ qkv, const float* __restrict__ q,
                                 const float* __restrict__ kv, const float* __restrict__ hp,
                                 const float* __restrict__ lp, float* __restrict__ W) {
    int i4 = (blockIdx.x * 256 + threadIdx.x) * 4;
    const float* src; int off;
    if      (i4 < W_Q)  { src = qkv; off = W_QKV; }
    else if (i4 < W_KV) { src = q;   off = W_Q;   }
    else if (i4 < W_HP) { src = kv;  off = W_KV;  }
    else if (i4 < W_LP) { src = hp;  off = W_HP;  }
    else                { src = lp;  off = W_LP;  }
    float4 v = *(const float4*)(src + (i4 - off));
    *(uint4*)(W + i4) = f2tf4(v);
}

// ---------------------------------------------------------------------------
// 1. Input transpose: x (B, 512, 4096) -> X (B, 4096, 512), tf32-rounded
// ---------------------------------------------------------------------------
__global__ void transpose_in_kernel(const float* __restrict__ x, float* __restrict__ X) {
    __shared__ float t[32][33];
    const int b  = blockIdx.z;
    const int p0 = blockIdx.x * 32;
    const int c0 = blockIdx.y * 32;
    const int tx = threadIdx.x, ty = threadIdx.y;
    #pragma unroll
    for (int i = ty; i < 32; i += 8)
        t[i][tx] = x[(b * 512 + c0 + i) * 4096 + p0 + tx];
    __syncthreads();
    #pragma unroll
    for (int i = ty; i < 32; i += 8)
        X[(b * 4096 + p0 + i) * 512 + c0 + tx] = __uint_as_float(f2tf(t[tx][i]));
}

// ---------------------------------------------------------------------------
// 2. 2x2 average pool (output tf32-rounded)
// ---------------------------------------------------------------------------
__global__ void pool_kernel(const float* __restrict__ X, float* __restrict__ pooled) {
    int idx = blockIdx.x * 256 + threadIdx.x;
    int c = idx & 511;
    int r = idx >> 9;
    int b = r >> 10;
    int g = r & 1023;
    int gh = g >> 5, gw = g & 31;
    long base = (long)(b * 4096 + gh * 128 + gw * 2) * 512 + c;
    float s = X[base] + X[base + 512] + X[base + 64 * 512] + X[base + 64 * 512 + 512];
    pooled[idx] = __uint_as_float(f2tf(0.25f * s));
}

// ---------------------------------------------------------------------------
// 3. tf32 GEMM, cp.async 2-stage pipeline. Inputs must be tf32-rounded floats.
//    Block 128x128, 8 warps (2x4), warp tile 64x32, k-chunk 32.
//    mode 0: plain store; mode 1: tf32-rounded store;
//    mode 2: bias + transposed NCHW store into out at channel offset coff.
// ---------------------------------------------------------------------------
#define AS_SZ (128 * 40)
#define BS_SZ (32 * 136)
#define GEMM_SMEM (2 * (AS_SZ + BS_SZ) * 4)   // 75776 bytes

__global__ __launch_bounds__(256) void gemm_tf32(
    const float* __restrict__ A, const float* __restrict__ Bw,
    const float* __restrict__ bias, float* __restrict__ C,
    int M, int N, int K, int mode, int coff)
{
    extern __shared__ unsigned sh[];

    const int tid = threadIdx.x;
    const int lane = tid & 31, w = tid >> 5;
    const int g = lane >> 2, t = lane & 3;
    const int wm = (w >> 2) * 64, wn = (w & 3) * 32;
    const int bn = blockIdx.x * 128, bm = blockIdx.y * 128;

    float c[4][4][4];
    #pragma unroll
    for (int mt = 0; mt < 4; mt++)
        #pragma unroll
        for (int nt = 0; nt < 4; nt++)
            #pragma unroll
            for (int i = 0; i < 4; i++) c[mt][nt][i] = 0.f;

    // prologue: stage 0
    {
        unsigned* As = sh;
        unsigned* Bs = sh + AS_SZ;
        #pragma unroll
        for (int i = 0; i < 4; i++) {
            int idx = tid + i * 256;
            int m = idx >> 3, kc = (idx & 7) * 4;
            cp16(&As[m * 40 + kc], A + (long)(bm + m) * K + kc);
        }
        #pragma unroll
        for (int i = 0; i < 4; i++) {
            int idx = tid + i * 256;
            int kr = idx >> 5, nc = (idx & 31) * 4;
            cp16(&Bs[kr * 136 + nc], Bw + (long)kr * N + bn + nc);
        }
        CP_COMMIT();
    }

    const int NK = K >> 5;
    for (int kc = 0; kc < NK; kc++) {
        if (kc + 1 < NK) {
            int k0 = (kc + 1) * 32;
            unsigned* As = sh + ((kc + 1) & 1) * (AS_SZ + BS_SZ);
            unsigned* Bs = As + AS_SZ;
            #pragma unroll
            for (int i = 0; i < 4; i++) {
                int idx = tid + i * 256;
                int m = idx >> 3, kcc = (idx & 7) * 4;
                cp16(&As[m * 40 + kcc], A + (long)(bm + m) * K + k0 + kcc);
            }
            #pragma unroll
            for (int i = 0; i < 4; i++) {
                int idx = tid + i * 256;
                int kr = idx >> 5, nc = (idx & 31) * 4;
                cp16(&Bs[kr * 136 + nc], Bw + (long)(k0 + kr) * N + bn + nc);
            }
            CP_COMMIT();
            CP_WAIT1();
        } else {
            CP_WAIT0();
        }
        __syncthreads();

        unsigned* As = sh + (kc & 1) * (AS_SZ + BS_SZ);
        unsigned* Bs = As + AS_SZ;
        #pragma unroll
        for (int ks = 0; ks < 4; ks++) {
            unsigned a[4][4], bf[4][2];
            #pragma unroll
            for (int mt = 0; mt < 4; mt++) {
                int r = wm + mt * 16 + g;
                a[mt][0] = As[r * 40 + ks * 8 + t];
                a[mt][1] = As[(r + 8) * 40 + ks * 8 + t];
                a[mt][2] = As[r * 40 + ks * 8 + t + 4];
                a[mt][3] = As[(r + 8) * 40 + ks * 8 + t + 4];
            }
            #pragma unroll
            for (int nt = 0; nt < 4; nt++) {
                bf[nt][0] = Bs[(ks * 8 + t) * 136 + wn + nt * 8 + g];
                bf[nt][1] = Bs[(ks * 8 + t + 4) * 136 + wn + nt * 8 + g];
            }
            #pragma unroll
            for (int mt = 0; mt < 4; mt++)
                #pragma unroll
                for (int nt = 0; nt < 4; nt++)
                    mma_tf32(c[mt][nt], a[mt], bf[nt][0], bf[nt][1]);
        }
        __syncthreads();
    }

    if (mode == 2) {
        // bias + transposed NCHW store: out[(b*512 + coff + bn + col)*4096 + pix]
        float* S = (float*)sh;     // [128 cols][132]
        #pragma unroll
        for (int nt = 0; nt < 4; nt++) {
            int col = wn + nt * 8 + 2 * t;
            float b0 = bias[bn + col], b1 = bias[bn + col + 1];
            #pragma unroll
            for (int mt = 0; mt < 4; mt++) {
                int r = wm + mt * 16 + g;
                S[col * 132 + r]           = c[mt][nt][0] + b0;
                S[(col + 1) * 132 + r]     = c[mt][nt][1] + b1;
                S[col * 132 + r + 8]       = c[mt][nt][2] + b0;
                S[(col + 1) * 132 + r + 8] = c[mt][nt][3] + b1;
            }
        }
        __syncthreads();
        const int b = bm >> 12;
        const int pix0 = bm & 4095;
        #pragma unroll
        for (int i = 0; i < 16; i++) {
            int idx = tid + i * 256;
            int cch = idx >> 5, p4 = (idx & 31) * 4;
            float4 v = *(const float4*)&S[cch * 132 + p4];
            *(float4*)(C + (long)(b * 512 + coff + bn + cch) * 4096 + pix0 + p4) = v;
        }
        return;
    }

    float bv[4][2];
    #pragma unroll
    for (int nt = 0; nt < 4; nt++) {
        bv[nt][0] = bias ? bias[bn + wn + nt * 8 + 2 * t]     : 0.f;
        bv[nt][1] = bias ? bias[bn + wn + nt * 8 + 2 * t + 1] : 0.f;
    }
    #pragma unroll
    for (int mt = 0; mt < 4; mt++) {
        int row = bm + wm + mt * 16 + g;
        #pragma unroll
        for (int nt = 0; nt < 4; nt++) {
            int col = bn + wn + nt * 8 + 2 * t;
            float2 lo, hi;
            lo.x = c[mt][nt][0] + bv[nt][0]; lo.y = c[mt][nt][1] + bv[nt][1];
            hi.x = c[mt][nt][2] + bv[nt][0]; hi.y = c[mt][nt][3] + bv[nt][1];
            if (mode == 1) {
                lo.x = __uint_as_float(f2tf(lo.x)); lo.y = __uint_as_float(f2tf(lo.y));
                hi.x = __uint_as_float(f2tf(hi.x)); hi.y = __uint_as_float(f2tf(hi.y));
            }
            *(float2*)(C + (long)row * N + col)       = lo;
            *(float2*)(C + (long)(row + 8) * N + col) = hi;
        }
    }
}

// ---------------------------------------------------------------------------
// 4. Hi-fi windowed attention (fp32, tiny). Output tf32-rounded.
// ---------------------------------------------------------------------------
__global__ void hi_attn_kernel(const float* __restrict__ QKV, float* __restrict__ HiOut) {
    __shared__ float qk[4][768];
    __shared__ float sS[4][16];
    __shared__ float sP[4][16];

    const int tid = threadIdx.x;
    const int bg = blockIdx.x;
    const int b = bg >> 10;
    const int g = bg & 1023;
    const int gh = g >> 5, gw = g & 31;
    const int rowbase = b * 4096;

    for (int i = tid; i < 4 * 192; i += 256) {
        int n = i / 192;
        int c4 = (i % 192) * 4;
        int pix = (2 * gh + (n >> 1)) * 64 + 2 * gw + (n & 1);
        *(float4*)&qk[n][c4] = *(const float4*)(QKV + (long)(rowbase + pix) * 768 + c4);
    }
    __syncthreads();

    const int head = tid >> 6;
    const int r = tid & 63;

    if (r < 16) {
        int n = r >> 2, m = r & 3;
        const float* qp = &qk[n][head * 64];
        const float* kp = &qk[m][256 + head * 64];
        float a = 0.f;
        #pragma unroll
        for (int d = 0; d < 64; d++) a = fmaf(qp[d], kp[d], a);
        sS[head][r] = a * SCALE;
    }
    __syncthreads();

    if (r < 4) {
        int n = r;
        float mx = sS[head][n * 4];
        #pragma unroll
        for (int m = 1; m < 4; m++) mx = fmaxf(mx, sS[head][n * 4 + m]);
        float e[4], sum = 0.f;
        #pragma unroll
        for (int m = 0; m < 4; m++) { e[m] = __expf(sS[head][n * 4 + m] - mx); sum += e[m]; }
        float inv = 1.f / sum;
        #pragma unroll
        for (int m = 0; m < 4; m++) sP[head][n * 4 + m] = e[m] * inv;
    }
    __syncthreads();

    const int d = r;
    #pragma unroll
    for (int n = 0; n < 4; n++) {
        float o = 0.f;
        #pragma unroll
        for (int m = 0; m < 4; m++)
            o = fmaf(sP[head][n * 4 + m], qk[m][512 + head * 64 + d], o);
        int pix = (2 * gh + (n >> 1)) * 64 + 2 * gw + (n & 1);
        HiOut[(long)(rowbase + pix) * 256 + head * 64 + d] = __uint_as_float(f2tf(o));
    }
}

// ---------------------------------------------------------------------------
// 5. Lo-fi flash attention, tf32 MMA. 256 threads (8 warps), 128 q-rows/block;
//    16 key tiles of 64. KV pre-rounded -> raw cp.async staging.
// ---------------------------------------------------------------------------
#define LOP 72
#define LO_SMEM ((128 * LOP + 2 * 64 * LOP) * 4)   // 73728 bytes

__global__ __launch_bounds__(256) void lo_attn_tf32(
    const float* __restrict__ Ql, const float* __restrict__ KVl,
    float* __restrict__ LoOut)
{
    extern __shared__ unsigned smu[];
    unsigned* Ps = smu;                 // [128][LOP] : Q staging, then P
    unsigned* Ks = smu + 128 * LOP;     // [64][LOP]
    unsigned* Vs = smu + (128 + 64) * LOP;

    const int tid = threadIdx.x;
    const int lane = tid & 31, w = tid >> 5;
    const int g = lane >> 2, t = lane & 3;
    const int qt = blockIdx.x, h = blockIdx.y, b = blockIdx.z;

    const float* Qbase = Ql  + (long)(b * 4096 + qt * 128) * 256 + h * 64;
    const float* Kbase = KVl + (long)(b * 1024) * 512 + h * 64;

    // stage Q (scaled by SCALE*log2e), round to tf32
    for (int idx = tid; idx < 128 * 16; idx += 256) {
        int q = idx >> 4, c4 = (idx & 15) * 4;
        float4 v = *(const float4*)(Qbase + (long)q * 256 + c4);
        v.x *= QSCALE; v.y *= QSCALE; v.z *= QSCALE; v.w *= QSCALE;
        *(uint4*)&Ps[q * LOP + c4] = f2tf4(v);
    }
    __syncthreads();

    const int r0 = w * 16 + g;
    unsigned Qa[8][4];
    #pragma unroll
    for (int kk = 0; kk < 8; kk++) {
        Qa[kk][0] = Ps[r0 * LOP + kk * 8 + t];
        Qa[kk][1] = Ps[(r0 + 8) * LOP + kk * 8 + t];
        Qa[kk][2] = Ps[r0 * LOP + kk * 8 + t + 4];
        Qa[kk][3] = Ps[(r0 + 8) * LOP + kk * 8 + t + 4];
    }

    float o[8][4];
    #pragma unroll
    for (int j = 0; j < 8; j++)
        #pragma unroll
        for (int i = 0; i < 4; i++) o[j][i] = 0.f;
    float m0 = -1e30f, m1 = -1e30f, l0 = 0.f, l1 = 0.f;

    for (int kt = 0; kt < 16; kt++) {
        __syncthreads();
        const float* Kt = Kbase + (long)(kt * 64) * 512;
        #pragma unroll
        for (int i = 0; i < 4; i++) {
            int idx = tid + i * 256;
            int key = idx >> 4, c4 = (idx & 15) * 4;
            const float* gp = Kt + (long)key * 512 + c4;
            cp16(&Ks[key * LOP + c4], gp);
            cp16(&Vs[key * LOP + c4], gp + 256);
        }
        CP_COMMIT();
        CP_WAIT0();
        __syncthreads();

        // S = Q K^T : per thread 8 n-tiles x 4 regs
        float s[8][4];
        #pragma unroll
        for (int j = 0; j < 8; j++) {
            s[j][0] = s[j][1] = s[j][2] = s[j][3] = 0.f;
            #pragma unroll
            for (int kk = 0; kk < 8; kk++) {
                unsigned b0 = Ks[(j * 8 + g) * LOP + kk * 8 + t];
                unsigned b1 = Ks[(j * 8 + g) * LOP + kk * 8 + t + 4];
                mma_tf32(s[j], Qa[kk], b0, b1);
            }
        }

        // online softmax (rows r0, r0+8); base-2 exp (scale folded into Q)
        float mx0 = -1e30f, mx1 = -1e30f;
        #pragma unroll
        for (int j = 0; j < 8; j++) {
            mx0 = fmaxf(mx0, fmaxf(s[j][0], s[j][1]));
            mx1 = fmaxf(mx1, fmaxf(s[j][2], s[j][3]));
        }
        mx0 = fmaxf(mx0, __shfl_xor_sync(0xffffffffu, mx0, 1));
        mx0 = fmaxf(mx0, __shfl_xor_sync(0xffffffffu, mx0, 2));
        mx1 = fmaxf(mx1, __shfl_xor_sync(0xffffffffu, mx1, 1));
        mx1 = fmaxf(mx1, __shfl_xor_sync(0xffffffffu, mx1, 2));
        float nm0 = fmaxf(m0, mx0), nm1 = fmaxf(m1, mx1);
        float a0 = ex2(m0 - nm0), a1 = ex2(m1 - nm1);
        float rs0 = 0.f, rs1 = 0.f;
        #pragma unroll
        for (int j = 0; j < 8; j++) {
            s[j][0] = ex2(s[j][0] - nm0); rs0 += s[j][0];
            s[j][1] = ex2(s[j][1] - nm0); rs0 += s[j][1];
            s[j][2] = ex2(s[j][2] - nm1); rs1 += s[j][2];
            s[j][3] = ex2(s[j][3] - nm1); rs1 += s[j][3];
        }
        rs0 += __shfl_xor_sync(0xffffffffu, rs0, 1);
        rs0 += __shfl_xor_sync(0xffffffffu, rs0, 2);
        rs1 += __shfl_xor_sync(0xffffffffu, rs1, 1);
        rs1 += __shfl_xor_sync(0xffffffffu, rs1, 2);
        l0 = l0 * a0 + rs0; m0 = nm0;
        l1 = l1 * a1 + rs1; m1 = nm1;
        #pragma unroll
        for (int j = 0; j < 8; j++) {
            o[j][0] *= a0; o[j][1] *= a0;
            o[j][2] *= a1; o[j][3] *= a1;
        }

        // store P (tf32) — each warp writes only its own 16 rows
        #pragma unroll
        for (int j = 0; j < 8; j++) {
            uint2 p0; p0.x = f2tf(s[j][0]); p0.y = f2tf(s[j][1]);
            uint2 p1; p1.x = f2tf(s[j][2]); p1.y = f2tf(s[j][3]);
            *(uint2*)&Ps[r0 * LOP + j * 8 + 2 * t]       = p0;
            *(uint2*)&Ps[(r0 + 8) * LOP + j * 8 + 2 * t] = p1;
        }
        __syncwarp();

        // O += P @ V
        #pragma unroll
        for (int kk = 0; kk < 8; kk++) {
            unsigned pa[4];
            pa[0] = Ps[r0 * LOP + kk * 8 + t];
            pa[1] = Ps[(r0 + 8) * LOP + kk * 8 + t];
            pa[2] = Ps[r0 * LOP + kk * 8 + t + 4];
            pa[3] = Ps[(r0 + 8) * LOP + kk * 8 + t + 4];
            #pragma unroll
            for (int j = 0; j < 8; j++) {
                unsigned b0 = Vs[(kk * 8 + t) * LOP + j * 8 + g];
                unsigned b1 = Vs[(kk * 8 + t + 4) * LOP + j * 8 + g];
                mma_tf32(o[j], pa, b0, b1);
            }
        }
    }

    // write normalized, tf32-rounded output (feeds proj GEMM)
    float inv0 = 1.f / l0, inv1 = 1.f / l1;
    long row = (long)(b * 4096 + qt * 128) + r0;
    #pragma unroll
    for (int j = 0; j < 8; j++) {
        int col = h * 64 + j * 8 + 2 * t;
        uint2 x0; x0.x = f2tf(o[j][0] * inv0); x0.y = f2tf(o[j][1] * inv0);
        uint2 x1; x1.x = f2tf(o[j][2] * inv1); x1.y = f2tf(o[j][3] * inv1);
        *(uint2*)(LoOut + row * 256 + col)       = x0;
        *(uint2*)(LoOut + (row + 8) * 256 + col) = x1;
    }
}

// ---------------------------------------------------------------------------
// Launch
// ---------------------------------------------------------------------------
extern "C" void kernel_launch(void* const* d_in, const int* in_sizes, int n_in,
                              void* d_out, int out_size)
{
    const float* x        = (const float*)d_in[0];
    const float* h_qkv_w  = (const float*)d_in[1];
    const float* h_proj_w = (const float*)d_in[2];
    const float* h_proj_b = (const float*)d_in[3];
    const float* l_q_w    = (const float*)d_in[4];
    const float* l_kv_w   = (const float*)d_in[5];
    const float* l_proj_w = (const float*)d_in[6];
    const float* l_proj_b = (const float*)d_in[7];
    float* out = (float*)d_out;

    float *X, *P, *W, *QKV, *Ql, *KVl, *HiO, *LoO;
    cudaGetSymbolAddress((void**)&X,   g_X);
    cudaGetSymbolAddress((void**)&P,   g_pooled);
    cudaGetSymbolAddress((void**)&W,   g_W);
    cudaGetSymbolAddress((void**)&QKV, g_QKV);
    cudaGetSymbolAddress((void**)&Ql,  g_Ql);
    cudaGetSymbolAddress((void**)&KVl, g_KVl);
    cudaGetSymbolAddress((void**)&HiO, g_HiOut);
    cudaGetSymbolAddress((void**)&LoO, g_LoOut);

    cudaFuncSetAttribute(gemm_tf32, cudaFuncAttributeMaxDynamicSharedMemorySize, GEMM_SMEM);
    cudaFuncSetAttribute(lo_attn_tf32, cudaFuncAttributeMaxDynamicSharedMemorySize, LO_SMEM);

    convert_w_kernel<<<W_TOT / 1024, 256>>>(h_qkv_w, l_q_w, l_kv_w, h_proj_w, l_proj_w, W);
    transpose_in_kernel<<<dim3(128, 16, 4), dim3(32, 8)>>>(x, X);
    pool_kernel<<<8192, 256>>>(X, P);

    gemm_tf32<<<dim3(6, 128), 256, GEMM_SMEM>>>(X, W + W_QKV, nullptr, QKV, BHW, 768, 512, 0, 0);
    gemm_tf32<<<dim3(2, 128), 256, GEMM_SMEM>>>(X, W + W_Q,   nullptr, Ql,  BHW, 256, 512, 0, 0);
    gemm_tf32<<<dim3(4, 32),  256, GEMM_SMEM>>>(P, W + W_KV,  nullptr, KVl, BG,  512, 512, 1, 0);

    hi_attn_kernel<<<4096, 256>>>(QKV, HiO);
    lo_attn_tf32<<<dim3(32, 4, 4), 256, LO_SMEM>>>(Ql, KVl, LoO);

    // proj GEMMs write transposed NCHW directly into the output (concat fused)
    gemm_tf32<<<dim3(2, 128), 256, GEMM_SMEM>>>(HiO, W + W_HP, h_proj_b, out, BHW, 256, 256, 2, 0);
    gemm_tf32<<<dim3(2, 128), 256, GEMM_SMEM>>>(LoO, W + W_LP, l_proj_b, out, BHW, 256, 256, 2, 256);
}